// round 5
// baseline (speedup 1.0000x reference)
#include <cuda_runtime.h>
#include <math.h>

#define BSZ 2
#define SEQ 1024
#define HID 4096
#define NH 32
#define KVH 8
#define HD 128
#define ROWS (BSZ*SEQ)      // 2048
#define KVD (KVH*HD)        // 1024

__device__ float g_Q[ROWS*HID];
__device__ float g_K[ROWS*KVD];
__device__ float g_V[ROWS*KVD];
__device__ float g_A[ROWS*HID];

__device__ __forceinline__ float* pick_buf(int id) {
    switch (id) {
        case 0: return g_Q;
        case 1: return g_K;
        case 2: return g_V;
        default: return g_A;
    }
}

// ---------------- SGEMM: C[M,N] = A[M,K] @ B[N,K]^T (both row-major, K-contiguous) ----
// a_id / c_id < 0 : use external pointer; >= 0 : use internal scratch buffer.
__global__ __launch_bounds__(256) void sgemm_nt(const float* __restrict__ Aext,
                                                const float* __restrict__ B,
                                                float* __restrict__ Cext,
                                                int M, int N, int K,
                                                int a_id, int c_id) {
    const float* A = (a_id < 0) ? Aext : pick_buf(a_id);
    float* C = (c_id < 0) ? Cext : pick_buf(c_id);
    const int BM = 128, BN = 128, BK = 8;
    __shared__ float As[BK][BM];
    __shared__ float Bs[BK][BN];
    int tid = threadIdx.x;
    int lr = tid >> 1;            // 0..127 : tile row being loaded
    int lc = (tid & 1) * 4;       // 0 or 4 : k offset
    int ty = tid >> 4;            // 0..15
    int tx = tid & 15;            // 0..15
    const float* Ab = A + (size_t)blockIdx.y * BM * K;
    const float* Bb = B + (size_t)blockIdx.x * BN * K;
    float acc[8][8];
#pragma unroll
    for (int i = 0; i < 8; i++)
#pragma unroll
        for (int j = 0; j < 8; j++) acc[i][j] = 0.f;

    for (int k0 = 0; k0 < K; k0 += BK) {
        float4 a4 = *(const float4*)(Ab + (size_t)lr * K + k0 + lc);
        float4 b4 = *(const float4*)(Bb + (size_t)lr * K + k0 + lc);
        As[lc + 0][lr] = a4.x; As[lc + 1][lr] = a4.y; As[lc + 2][lr] = a4.z; As[lc + 3][lr] = a4.w;
        Bs[lc + 0][lr] = b4.x; Bs[lc + 1][lr] = b4.y; Bs[lc + 2][lr] = b4.z; Bs[lc + 3][lr] = b4.w;
        __syncthreads();
#pragma unroll
        for (int k = 0; k < BK; k++) {
            float4 a0 = ((const float4*)As[k])[ty * 2];
            float4 a1 = ((const float4*)As[k])[ty * 2 + 1];
            float4 b0 = ((const float4*)Bs[k])[tx * 2];
            float4 b1 = ((const float4*)Bs[k])[tx * 2 + 1];
            float ar[8] = {a0.x, a0.y, a0.z, a0.w, a1.x, a1.y, a1.z, a1.w};
            float br[8] = {b0.x, b0.y, b0.z, b0.w, b1.x, b1.y, b1.z, b1.w};
#pragma unroll
            for (int i = 0; i < 8; i++)
#pragma unroll
                for (int j = 0; j < 8; j++) acc[i][j] += ar[i] * br[j];
        }
        __syncthreads();
    }
    float* Cb = C + (size_t)(blockIdx.y * BM + ty * 8) * N + blockIdx.x * BN + tx * 8;
#pragma unroll
    for (int i = 0; i < 8; i++) {
        float4 c0 = make_float4(acc[i][0], acc[i][1], acc[i][2], acc[i][3]);
        float4 c1 = make_float4(acc[i][4], acc[i][5], acc[i][6], acc[i][7]);
        *(float4*)(Cb + (size_t)i * N) = c0;
        *(float4*)(Cb + (size_t)i * N + 4) = c1;
    }
}

// ---------------- bitonic sort in shared memory (ascending) ----------------
__device__ __forceinline__ void bitonic_sort(float* s, int n) {
    for (int k = 2; k <= n; k <<= 1) {
        for (int j = k >> 1; j > 0; j >>= 1) {
            __syncthreads();
            for (int i = threadIdx.x; i < n; i += blockDim.x) {
                int ixj = i ^ j;
                if (ixj > i) {
                    float a = s[i], b = s[ixj];
                    bool up = ((i & k) == 0);
                    if ((a > b) == up) { s[i] = b; s[ixj] = a; }
                }
            }
        }
    }
    __syncthreads();
}

// ---------------- fake_quant_sparse on K: axis=0 (per column over 2048 rows) --------
__global__ __launch_bounds__(512) void quant_k_kernel() {
    __shared__ float s[2048];
    __shared__ float red[64];
    __shared__ float stats[3];
    int col = blockIdx.x;
    int tid = threadIdx.x;
    float xv[4];
#pragma unroll
    for (int m = 0; m < 4; m++) {
        int i = tid + 512 * m;
        xv[m] = g_K[(size_t)i * KVD + col];
        s[i] = xv[m];
    }
    bitonic_sort(s, 2048);
    if (tid == 0) {
        float posU = 0.9995f * 2047.0f;
        int iU = (int)posU; float frU = posU - (float)iU;
        float posL = 0.0005f * 2047.0f;
        int iL = (int)posL; float frL = posL - (float)iL;
        stats[0] = s[iL] * (1.0f - frL) + s[iL + 1] * frL;   // lower
        stats[1] = s[iU] * (1.0f - frU) + s[iU + 1] * frU;   // upper
        stats[2] = s[1023];                                   // lower median
    }
    __syncthreads();
    float lower = stats[0], upper = stats[1], med = stats[2];
    float mx = -1e30f, mn = 1e30f;
    bool msk[4];
#pragma unroll
    for (int m = 0; m < 4; m++) {
        msk[m] = (xv[m] <= lower) || (xv[m] >= upper);
        float tmp = msk[m] ? med : xv[m];
        mx = fmaxf(mx, tmp);
        mn = fminf(mn, tmp);
    }
#pragma unroll
    for (int o = 16; o > 0; o >>= 1) {
        mx = fmaxf(mx, __shfl_xor_sync(0xffffffffu, mx, o));
        mn = fminf(mn, __shfl_xor_sync(0xffffffffu, mn, o));
    }
    if ((tid & 31) == 0) { red[tid >> 5] = mx; red[32 + (tid >> 5)] = mn; }
    __syncthreads();
    if (tid == 0) {
        float M = -1e30f, Nn = 1e30f;
        for (int w = 0; w < 16; w++) { M = fmaxf(M, red[w]); Nn = fminf(Nn, red[32 + w]); }
        red[0] = M; red[32] = Nn;
    }
    __syncthreads();
    mx = red[0]; mn = red[32];
    float qx = 15.0f / (mx - mn);
    float offset = mn * qx;
#pragma unroll
    for (int m = 0; m < 4; m++) {
        if (!msk[m]) {
            float q = rintf(qx * xv[m] - offset);     // round-half-even like jnp.round
            q = fminf(fmaxf(q, 0.0f), 15.0f);
            g_K[(size_t)(tid + 512 * m) * KVD + col] = (q + offset) / qx;
        }
        // masked elements keep original x (in-place, untouched)
    }
}

// ---------------- fake_quant_sparse on V: axis=-1 (per row over 1024 dims) ----------
__global__ __launch_bounds__(256) void quant_v_kernel() {
    __shared__ float s[1024];
    __shared__ float red[64];
    __shared__ float stats[3];
    int r = blockIdx.x;
    int tid = threadIdx.x;
    float* row = g_V + (size_t)r * KVD;
    float xv[4];
#pragma unroll
    for (int m = 0; m < 4; m++) {
        int i = tid + 256 * m;
        xv[m] = row[i];
        s[i] = xv[m];
    }
    bitonic_sort(s, 1024);
    if (tid == 0) {
        float posU = 0.9995f * 1023.0f;
        int iU = (int)posU; float frU = posU - (float)iU;
        float posL = 0.0005f * 1023.0f;
        int iL = (int)posL; float frL = posL - (float)iL;
        stats[0] = s[iL] * (1.0f - frL) + s[iL + 1] * frL;
        stats[1] = s[iU] * (1.0f - frU) + s[iU + 1] * frU;
        stats[2] = s[511];
    }
    __syncthreads();
    float lower = stats[0], upper = stats[1], med = stats[2];
    float mx = -1e30f, mn = 1e30f;
    bool msk[4];
#pragma unroll
    for (int m = 0; m < 4; m++) {
        msk[m] = (xv[m] <= lower) || (xv[m] >= upper);
        float tmp = msk[m] ? med : xv[m];
        mx = fmaxf(mx, tmp);
        mn = fminf(mn, tmp);
    }
#pragma unroll
    for (int o = 16; o > 0; o >>= 1) {
        mx = fmaxf(mx, __shfl_xor_sync(0xffffffffu, mx, o));
        mn = fminf(mn, __shfl_xor_sync(0xffffffffu, mn, o));
    }
    if ((tid & 31) == 0) { red[tid >> 5] = mx; red[32 + (tid >> 5)] = mn; }
    __syncthreads();
    if (tid == 0) {
        float M = -1e30f, Nn = 1e30f;
        for (int w = 0; w < 8; w++) { M = fmaxf(M, red[w]); Nn = fminf(Nn, red[32 + w]); }
        red[0] = M; red[32] = Nn;
    }
    __syncthreads();
    mx = red[0]; mn = red[32];
    float qx = 15.0f / (mx - mn);
    float offset = mn * qx;
#pragma unroll
    for (int m = 0; m < 4; m++) {
        if (!msk[m]) {
            float q = rintf(qx * xv[m] - offset);
            q = fminf(fmaxf(q, 0.0f), 15.0f);
            row[tid + 256 * m] = (q + offset) / qx;
        }
    }
}

// ---------------- RoPE (in place). which=0 -> g_Q (32 heads), which=1 -> g_K (8 heads) ----
__global__ void rope_kernel(int which, int nheads, int total) {
    int idx = blockIdx.x * blockDim.x + threadIdx.x;
    if (idx >= total) return;
    float* X = (which == 0) ? g_Q : g_K;
    int d = idx & 63;
    int t2 = idx >> 6;
    int h = t2 % nheads;
    int r = t2 / nheads;
    int pos = r & (SEQ - 1);
    double inv = exp(-((double)d / 64.0) * log(10000.0));
    double fr = (double)pos * inv;
    float c = (float)cos(fr);
    float sn = (float)sin(fr);
    float* p = X + (size_t)r * nheads * HD + h * HD + d;
    float x1 = p[0], x2 = p[64];
    p[0] = x1 * c - x2 * sn;
    p[64] = x2 * c + x1 * sn;
}

// ---------------- Causal GQA flash attention, fp32, 32KB static smem ----------------
// grid: (SEQ/64, NH, BSZ), block 256. 4 threads per query row; Q and scores in registers.
__global__ __launch_bounds__(256) void attn_kernel() {
    __shared__ float Ks[32 * HD];   // 16 KB, [j][d] row-major
    __shared__ float Vs[32 * HD];   // 16 KB
    int qt = blockIdx.x, h = blockIdx.y, b = blockIdx.z;
    int kvh = h >> 2;
    int tid = threadIdx.x;
    int row = tid >> 2;       // 0..63 : query row within tile
    int quad = tid & 3;       // owns dims [quad*32, quad*32+32)
    const float scale = 0.08838834764831843f;  // 1/sqrt(128)
    int qglob = qt * 64 + row;

    // Q slice for this thread: 32 floats in registers
    float4 q4[8];
    const float4* qp = (const float4*)(g_Q + (size_t)(b * SEQ + qglob) * HID + h * HD + quad * 32);
#pragma unroll
    for (int x = 0; x < 8; x++) q4[x] = qp[x];

    float4 acc[8];
#pragma unroll
    for (int x = 0; x < 8; x++) acc[x] = make_float4(0.f, 0.f, 0.f, 0.f);
    float m_i = -1e30f, l_i = 0.f;

    int nchunk = 2 * qt + 2;   // keys up to (qt+1)*64 in chunks of 32
    for (int kt = 0; kt < nchunk; kt++) {
        __syncthreads();
        // stage 32 K rows + 32 V rows (each thread: 4 float4 per matrix)
        for (int e = tid; e < 32 * HD / 4; e += 256) {
            size_t base = (size_t)(b * SEQ + kt * 32 + (e >> 5)) * KVD + kvh * HD + (e & 31) * 4;
            ((float4*)Ks)[e] = *(const float4*)(g_K + base);
            ((float4*)Vs)[e] = *(const float4*)(g_V + base);
        }
        __syncthreads();

        // scores for this row's 32 keys; each thread ends up with the full row segment
        float p[32];
        float m_t = -1e30f;
#pragma unroll
        for (int j = 0; j < 32; j++) {
            const float4* kr = ((const float4*)Ks) + j * 32 + quad * 8;
            float s = 0.f;
#pragma unroll
            for (int x = 0; x < 8; x++) {
                float4 kv = kr[x];
                s += q4[x].x * kv.x + q4[x].y * kv.y + q4[x].z * kv.z + q4[x].w * kv.w;
            }
            s += __shfl_xor_sync(0xffffffffu, s, 1);
            s += __shfl_xor_sync(0xffffffffu, s, 2);
            s *= scale;
            if (kt * 32 + j > qglob) s = -1e30f;
            p[j] = s;
            m_t = fmaxf(m_t, s);
        }

        float m_new = fmaxf(m_i, m_t);
        float corr = expf(m_i - m_new);
        float lsum = 0.f;
#pragma unroll
        for (int j = 0; j < 32; j++) {
            p[j] = expf(p[j] - m_new);
            lsum += p[j];
        }
        l_i = l_i * corr + lsum;
        m_i = m_new;
#pragma unroll
        for (int x = 0; x < 8; x++) {
            acc[x].x *= corr; acc[x].y *= corr; acc[x].z *= corr; acc[x].w *= corr;
        }
#pragma unroll
        for (int j = 0; j < 32; j++) {
            float pj = p[j];
            const float4* vr = ((const float4*)Vs) + j * 32 + quad * 8;
#pragma unroll
            for (int x = 0; x < 8; x++) {
                float4 vv = vr[x];
                acc[x].x += pj * vv.x; acc[x].y += pj * vv.y;
                acc[x].z += pj * vv.z; acc[x].w += pj * vv.w;
            }
        }
    }
    float invl = 1.0f / l_i;
    float* op = g_A + (size_t)(b * SEQ + qglob) * HID + h * HD + quad * 32;
#pragma unroll
    for (int x = 0; x < 8; x++) {
        float4 vv = acc[x];
        vv.x *= invl; vv.y *= invl; vv.z *= invl; vv.w *= invl;
        *(float4*)(op + x * 4) = vv;
    }
}

extern "C" void kernel_launch(void* const* d_in, const int* in_sizes, int n_in,
                              void* d_out, int out_size) {
    const float* hidden = (const float*)d_in[0];
    const float* Wq = (const float*)d_in[1];
    const float* Wk = (const float*)d_in[2];
    const float* Wv = (const float*)d_in[3];
    const float* Wo = (const float*)d_in[4];
    float* out = (float*)d_out;

    // projections: C internal (a_id=-1 external A, c_id selects scratch)
    sgemm_nt<<<dim3(HID / 128, ROWS / 128), 256>>>(hidden, Wq, nullptr, ROWS, HID, HID, -1, 0);
    sgemm_nt<<<dim3(KVD / 128, ROWS / 128), 256>>>(hidden, Wk, nullptr, ROWS, KVD, HID, -1, 1);
    sgemm_nt<<<dim3(KVD / 128, ROWS / 128), 256>>>(hidden, Wv, nullptr, ROWS, KVD, HID, -1, 2);

    // fake-quant (in place on g_K / g_V)
    quant_k_kernel<<<KVD, 512>>>();
    quant_v_kernel<<<ROWS, 256>>>();

    // RoPE on Q (32 heads) and quantized K (8 heads)
    int totQ = ROWS * NH * 64;
    int totK = ROWS * KVH * 64;
    rope_kernel<<<(totQ + 255) / 256, 256>>>(0, NH, totQ);
    rope_kernel<<<(totK + 255) / 256, 256>>>(1, KVH, totK);

    // attention: g_Q, g_K, g_V -> g_A (static 32KB smem, no attribute call needed)
    attn_kernel<<<dim3(SEQ / 64, NH, BSZ), 256>>>();

    // output projection: A internal, C external
    sgemm_nt<<<dim3(HID / 128, ROWS / 128), 256>>>(nullptr, Wo, out, ROWS, HID, HID, 3, -1);
}

// round 15
// speedup vs baseline: 1.2640x; 1.2640x over previous
#include <cuda_runtime.h>
#include <cuda_bf16.h>
#include <math.h>
#include <stdint.h>

#define BSZ 2
#define SEQ 1024
#define HID 4096
#define NH 32
#define KVH 8
#define HD 128
#define ROWS (BSZ*SEQ)      // 2048
#define KVD (KVH*HD)        // 1024
#define K3 (3*HID)          // 12288

// fp32 scratch
__device__ float g_Q[ROWS*HID];
__device__ float g_K[ROWS*KVD];
__device__ float g_V[ROWS*KVD];
__device__ float g_A[ROWS*HID];
// bf16 split buffers (only Q/O path)
__device__ __nv_bfloat16 g_hs [ROWS*(size_t)K3];   // split hidden  (A-style)
__device__ __nv_bfloat16 g_as2[ROWS*(size_t)K3];   // split attn out (A-style)
__device__ __nv_bfloat16 g_wq [HID*(size_t)K3];    // split weights (B-style)
__device__ __nv_bfloat16 g_wo [HID*(size_t)K3];

__device__ __forceinline__ uint32_t s2u(const void* p) {
    uint32_t a;
    asm("{ .reg .u64 t; cvta.to.shared.u64 t, %1; cvt.u32.u64 %0, t; }" : "=r"(a) : "l"(p));
    return a;
}

__device__ __forceinline__ void cp16(uint32_t dst, const void* src) {
    asm volatile("cp.async.cg.shared.global [%0], [%1], 16;" :: "r"(dst), "l"(src));
}

// ---------------- bf16 split: X[rows,4096] f32 -> Y[rows,3*4096] bf16 ----------------
// mode 0 (A-side): [hi | lo | hi]   mode 1 (B-side): [hi | hi | lo]
__global__ void split_kernel(const float* __restrict__ Xext, int in_id, int out_id,
                             int mode, long total) {
    long i = (long)blockIdx.x * blockDim.x + threadIdx.x;
    if (i >= total) return;
    const float* X = (in_id < 0) ? Xext : g_A;
    __nv_bfloat16* Y;
    switch (out_id) {
        case 0: Y = g_hs; break;
        case 1: Y = g_wq; break;
        case 4: Y = g_wo; break;
        default: Y = g_as2; break;
    }
    long r = i >> 12;            // / 4096
    long c = i & 4095;
    float x = X[i];
    __nv_bfloat16 hi = __float2bfloat16(x);
    __nv_bfloat16 lo = __float2bfloat16(x - __bfloat162float(hi));
    __nv_bfloat16* row = Y + r * (size_t)K3;
    if (mode == 0) {
        row[c] = hi; row[HID + c] = lo; row[2 * HID + c] = hi;
    } else {
        row[c] = hi; row[HID + c] = hi; row[2 * HID + c] = lo;
    }
}

// ---------------- fp32 SGEMM (bit-identical to R5 path): C = A @ B^T ----------------
__global__ __launch_bounds__(256) void sgemm_nt(const float* __restrict__ A,
                                                const float* __restrict__ B,
                                                int c_id, int M, int N, int K) {
    float* C = (c_id == 1) ? g_K : g_V;
    const int BM = 128, BN = 128, BK = 8;
    __shared__ float As[BK][BM];
    __shared__ float Bs[BK][BN];
    int tid = threadIdx.x;
    int lr = tid >> 1;
    int lc = (tid & 1) * 4;
    int ty = tid >> 4;
    int tx = tid & 15;
    const float* Ab = A + (size_t)blockIdx.y * BM * K;
    const float* Bb = B + (size_t)blockIdx.x * BN * K;
    float acc[8][8];
#pragma unroll
    for (int i = 0; i < 8; i++)
#pragma unroll
        for (int j = 0; j < 8; j++) acc[i][j] = 0.f;

    for (int k0 = 0; k0 < K; k0 += BK) {
        float4 a4 = *(const float4*)(Ab + (size_t)lr * K + k0 + lc);
        float4 b4 = *(const float4*)(Bb + (size_t)lr * K + k0 + lc);
        As[lc + 0][lr] = a4.x; As[lc + 1][lr] = a4.y; As[lc + 2][lr] = a4.z; As[lc + 3][lr] = a4.w;
        Bs[lc + 0][lr] = b4.x; Bs[lc + 1][lr] = b4.y; Bs[lc + 2][lr] = b4.z; Bs[lc + 3][lr] = b4.w;
        __syncthreads();
#pragma unroll
        for (int k = 0; k < BK; k++) {
            float4 a0 = ((const float4*)As[k])[ty * 2];
            float4 a1 = ((const float4*)As[k])[ty * 2 + 1];
            float4 b0 = ((const float4*)Bs[k])[tx * 2];
            float4 b1 = ((const float4*)Bs[k])[tx * 2 + 1];
            float ar[8] = {a0.x, a0.y, a0.z, a0.w, a1.x, a1.y, a1.z, a1.w};
            float br[8] = {b0.x, b0.y, b0.z, b0.w, b1.x, b1.y, b1.z, b1.w};
#pragma unroll
            for (int i = 0; i < 8; i++)
#pragma unroll
                for (int j = 0; j < 8; j++) acc[i][j] += ar[i] * br[j];
        }
        __syncthreads();
    }
    float* Cb = C + (size_t)(blockIdx.y * BM + ty * 8) * N + blockIdx.x * BN + tx * 8;
#pragma unroll
    for (int i = 0; i < 8; i++) {
        float4 c0 = make_float4(acc[i][0], acc[i][1], acc[i][2], acc[i][3]);
        float4 c1 = make_float4(acc[i][4], acc[i][5], acc[i][6], acc[i][7]);
        *(float4*)(Cb + (size_t)i * N) = c0;
        *(float4*)(Cb + (size_t)i * N + 4) = c1;
    }
}

// ---------------- HMMA bf16 GEMM: C[M,N] = A[M,K3] @ B[N,K3]^T (Q and O only) -------
#define SROWB 80            // bytes per smem row
#define ABUF_B 10240        // bytes per A (or B) buffer (128*80)
#define STAGE_B 20480       // bytes per stage (A+B)

__global__ __launch_bounds__(256) void bgemm_mma(int a_id, int b_id, int c_id,
                                                 float* __restrict__ Cext, int N) {
    __shared__ __align__(16) unsigned char smbuf[2 * STAGE_B];
    const __nv_bfloat16* A = (a_id == 0) ? g_hs : g_as2;
    const __nv_bfloat16* B = (b_id == 0) ? g_wq : g_wo;
    float* C = (c_id < 0) ? Cext : g_Q;

    const int tid = threadIdx.x;
    const int lane = tid & 31;
    const int wid = tid >> 5;
    const int wm = (wid & 1) * 64;
    const int wn = (wid >> 1) * 32;
    const int m0g = blockIdx.y * 128;
    const int n0g = blockIdx.x * 128;
    const uint32_t smb = s2u(smbuf);

    const int lc = tid & 3;
    const int lr = tid >> 2;
    const __nv_bfloat16* aSrc0 = A + (size_t)(m0g + lr) * K3 + lc * 8;
    const __nv_bfloat16* aSrc1 = A + (size_t)(m0g + lr + 64) * K3 + lc * 8;
    const __nv_bfloat16* bSrc0 = B + (size_t)(n0g + lr) * K3 + lc * 8;
    const __nv_bfloat16* bSrc1 = B + (size_t)(n0g + lr + 64) * K3 + lc * 8;
    const uint32_t dA0 = (uint32_t)(lr * SROWB + lc * 16);
    const uint32_t dA1 = dA0 + 64 * SROWB;

    uint32_t aAddr[4], bAddr[4];
#pragma unroll
    for (int mt = 0; mt < 4; mt++)
        aAddr[mt] = smb + (uint32_t)((wm + mt * 16 + (lane & 15)) * SROWB + (lane >> 4) * 16);
#pragma unroll
    for (int nt = 0; nt < 4; nt++)
        bAddr[nt] = smb + ABUF_B +
                    (uint32_t)((wn + nt * 8 + (lane & 7)) * SROWB + ((lane >> 3) & 1) * 16);

    float acc[4][4][4];
#pragma unroll
    for (int mt = 0; mt < 4; mt++)
#pragma unroll
        for (int nt = 0; nt < 4; nt++)
#pragma unroll
            for (int x = 0; x < 4; x++) acc[mt][nt][x] = 0.f;

    const int NK = K3 / 32;   // 384

    {
        uint32_t sb = smb;
        cp16(sb + dA0, aSrc0);
        cp16(sb + dA1, aSrc1);
        cp16(sb + ABUF_B + dA0, bSrc0);
        cp16(sb + ABUF_B + dA1, bSrc1);
        asm volatile("cp.async.commit_group;");
    }

    for (int it = 0; it < NK; ++it) {
        const uint32_t boff = (uint32_t)(it & 1) * STAGE_B;
        if (it + 1 < NK) {
            const int k0 = (it + 1) * 32;
            const uint32_t sb = smb + (uint32_t)((it + 1) & 1) * STAGE_B;
            cp16(sb + dA0, aSrc0 + k0);
            cp16(sb + dA1, aSrc1 + k0);
            cp16(sb + ABUF_B + dA0, bSrc0 + k0);
            cp16(sb + ABUF_B + dA1, bSrc1 + k0);
            asm volatile("cp.async.commit_group;");
            asm volatile("cp.async.wait_group %0;" :: "n"(1));
        } else {
            asm volatile("cp.async.wait_group %0;" :: "n"(0));
        }
        __syncthreads();

#pragma unroll
        for (int kk = 0; kk < 2; kk++) {
            const uint32_t ko = boff + kk * 32;
            uint32_t a[4][4], b[4][2];
#pragma unroll
            for (int mt = 0; mt < 4; mt++) {
                asm volatile("ldmatrix.sync.aligned.m8n8.x4.shared.b16 {%0,%1,%2,%3}, [%4];"
                             : "=r"(a[mt][0]), "=r"(a[mt][1]), "=r"(a[mt][2]), "=r"(a[mt][3])
                             : "r"(aAddr[mt] + ko));
            }
#pragma unroll
            for (int nt = 0; nt < 4; nt++) {
                asm volatile("ldmatrix.sync.aligned.m8n8.x2.shared.b16 {%0,%1}, [%2];"
                             : "=r"(b[nt][0]), "=r"(b[nt][1])
                             : "r"(bAddr[nt] + ko));
            }
#pragma unroll
            for (int mt = 0; mt < 4; mt++) {
#pragma unroll
                for (int nt = 0; nt < 4; nt++) {
                    asm volatile(
                        "mma.sync.aligned.m16n8k16.row.col.f32.bf16.bf16.f32 "
                        "{%0,%1,%2,%3}, {%4,%5,%6,%7}, {%8,%9}, {%0,%1,%2,%3};"
                        : "+f"(acc[mt][nt][0]), "+f"(acc[mt][nt][1]),
                          "+f"(acc[mt][nt][2]), "+f"(acc[mt][nt][3])
                        : "r"(a[mt][0]), "r"(a[mt][1]), "r"(a[mt][2]), "r"(a[mt][3]),
                          "r"(b[nt][0]), "r"(b[nt][1]));
                }
            }
        }
        __syncthreads();
    }

#pragma unroll
    for (int mt = 0; mt < 4; mt++) {
        int r0 = m0g + wm + mt * 16 + (lane >> 2);
#pragma unroll
        for (int nt = 0; nt < 4; nt++) {
            int cc = n0g + wn + nt * 8 + (lane & 3) * 2;
            float2 v0 = make_float2(acc[mt][nt][0], acc[mt][nt][1]);
            float2 v1 = make_float2(acc[mt][nt][2], acc[mt][nt][3]);
            *(float2*)(C + (size_t)r0 * N + cc) = v0;
            *(float2*)(C + (size_t)(r0 + 8) * N + cc) = v1;
        }
    }
}

// ---------------- bitonic sort in shared memory (ascending) ----------------
__device__ __forceinline__ void bitonic_sort(float* s, int n) {
    for (int k = 2; k <= n; k <<= 1) {
        for (int j = k >> 1; j > 0; j >>= 1) {
            __syncthreads();
            for (int i = threadIdx.x; i < n; i += blockDim.x) {
                int ixj = i ^ j;
                if (ixj > i) {
                    float a = s[i], b = s[ixj];
                    bool up = ((i & k) == 0);
                    if ((a > b) == up) { s[i] = b; s[ixj] = a; }
                }
            }
        }
    }
    __syncthreads();
}

// ---------------- fake_quant_sparse on K: axis=0 (per column over 2048 rows) --------
__global__ __launch_bounds__(512) void quant_k_kernel() {
    __shared__ float s[2048];
    __shared__ float red[64];
    __shared__ float stats[3];
    int col = blockIdx.x;
    int tid = threadIdx.x;
    float xv[4];
#pragma unroll
    for (int m = 0; m < 4; m++) {
        int i = tid + 512 * m;
        xv[m] = g_K[(size_t)i * KVD + col];
        s[i] = xv[m];
    }
    bitonic_sort(s, 2048);
    if (tid == 0) {
        float posU = 0.9995f * 2047.0f;
        int iU = (int)posU; float frU = posU - (float)iU;
        float posL = 0.0005f * 2047.0f;
        int iL = (int)posL; float frL = posL - (float)iL;
        stats[0] = s[iL] * (1.0f - frL) + s[iL + 1] * frL;
        stats[1] = s[iU] * (1.0f - frU) + s[iU + 1] * frU;
        stats[2] = s[1023];
    }
    __syncthreads();
    float lower = stats[0], upper = stats[1], med = stats[2];
    float mx = -1e30f, mn = 1e30f;
    bool msk[4];
#pragma unroll
    for (int m = 0; m < 4; m++) {
        msk[m] = (xv[m] <= lower) || (xv[m] >= upper);
        float tmp = msk[m] ? med : xv[m];
        mx = fmaxf(mx, tmp);
        mn = fminf(mn, tmp);
    }
#pragma unroll
    for (int o = 16; o > 0; o >>= 1) {
        mx = fmaxf(mx, __shfl_xor_sync(0xffffffffu, mx, o));
        mn = fminf(mn, __shfl_xor_sync(0xffffffffu, mn, o));
    }
    if ((tid & 31) == 0) { red[tid >> 5] = mx; red[32 + (tid >> 5)] = mn; }
    __syncthreads();
    if (tid == 0) {
        float M = -1e30f, Nn = 1e30f;
        for (int w = 0; w < 16; w++) { M = fmaxf(M, red[w]); Nn = fminf(Nn, red[32 + w]); }
        red[0] = M; red[32] = Nn;
    }
    __syncthreads();
    mx = red[0]; mn = red[32];
    float qx = 15.0f / (mx - mn);
    float offset = mn * qx;
#pragma unroll
    for (int m = 0; m < 4; m++) {
        if (!msk[m]) {
            float q = rintf(qx * xv[m] - offset);
            q = fminf(fmaxf(q, 0.0f), 15.0f);
            g_K[(size_t)(tid + 512 * m) * KVD + col] = (q + offset) / qx;
        }
    }
}

// ---------------- fake_quant_sparse on V: axis=-1 (per row over 1024 dims) ----------
__global__ __launch_bounds__(256) void quant_v_kernel() {
    __shared__ float s[1024];
    __shared__ float red[64];
    __shared__ float stats[3];
    int r = blockIdx.x;
    int tid = threadIdx.x;
    float* row = g_V + (size_t)r * KVD;
    float xv[4];
#pragma unroll
    for (int m = 0; m < 4; m++) {
        int i = tid + 256 * m;
        xv[m] = row[i];
        s[i] = xv[m];
    }
    bitonic_sort(s, 1024);
    if (tid == 0) {
        float posU = 0.9995f * 1023.0f;
        int iU = (int)posU; float frU = posU - (float)iU;
        float posL = 0.0005f * 1023.0f;
        int iL = (int)posL; float frL = posL - (float)iL;
        stats[0] = s[iL] * (1.0f - frL) + s[iL + 1] * frL;
        stats[1] = s[iU] * (1.0f - frU) + s[iU + 1] * frU;
        stats[2] = s[511];
    }
    __syncthreads();
    float lower = stats[0], upper = stats[1], med = stats[2];
    float mx = -1e30f, mn = 1e30f;
    bool msk[4];
#pragma unroll
    for (int m = 0; m < 4; m++) {
        msk[m] = (xv[m] <= lower) || (xv[m] >= upper);
        float tmp = msk[m] ? med : xv[m];
        mx = fmaxf(mx, tmp);
        mn = fminf(mn, tmp);
    }
#pragma unroll
    for (int o = 16; o > 0; o >>= 1) {
        mx = fmaxf(mx, __shfl_xor_sync(0xffffffffu, mx, o));
        mn = fminf(mn, __shfl_xor_sync(0xffffffffu, mn, o));
    }
    if ((tid & 31) == 0) { red[tid >> 5] = mx; red[32 + (tid >> 5)] = mn; }
    __syncthreads();
    if (tid == 0) {
        float M = -1e30f, Nn = 1e30f;
        for (int w = 0; w < 8; w++) { M = fmaxf(M, red[w]); Nn = fminf(Nn, red[32 + w]); }
        red[0] = M; red[32] = Nn;
    }
    __syncthreads();
    mx = red[0]; mn = red[32];
    float qx = 15.0f / (mx - mn);
    float offset = mn * qx;
#pragma unroll
    for (int m = 0; m < 4; m++) {
        if (!msk[m]) {
            float q = rintf(qx * xv[m] - offset);
            q = fminf(fmaxf(q, 0.0f), 15.0f);
            row[tid + 256 * m] = (q + offset) / qx;
        }
    }
}

// ---------------- RoPE (in place). which=0 -> g_Q (32 heads), which=1 -> g_K (8 heads) ----
__global__ void rope_kernel(int which, int nheads, int total) {
    int idx = blockIdx.x * blockDim.x + threadIdx.x;
    if (idx >= total) return;
    float* X = (which == 0) ? g_Q : g_K;
    int d = idx & 63;
    int t2 = idx >> 6;
    int h = t2 % nheads;
    int r = t2 / nheads;
    int pos = r & (SEQ - 1);
    double inv = exp(-((double)d / 64.0) * log(10000.0));
    double fr = (double)pos * inv;
    float c = (float)cos(fr);
    float sn = (float)sin(fr);
    float* p = X + (size_t)r * nheads * HD + h * HD + d;
    float x1 = p[0], x2 = p[64];
    p[0] = x1 * c - x2 * sn;
    p[64] = x2 * c + x1 * sn;
}

// ---------------- Causal GQA flash attention, fp32, 32KB static smem ----------------
__global__ __launch_bounds__(256) void attn_kernel() {
    __shared__ float Ks[32 * HD];
    __shared__ float Vs[32 * HD];
    int qt = blockIdx.x, h = blockIdx.y, b = blockIdx.z;
    int kvh = h >> 2;
    int tid = threadIdx.x;
    int row = tid >> 2;
    int quad = tid & 3;
    const float scale = 0.08838834764831843f;
    int qglob = qt * 64 + row;

    float4 q4[8];
    const float4* qp = (const float4*)(g_Q + (size_t)(b * SEQ + qglob) * HID + h * HD + quad * 32);
#pragma unroll
    for (int x = 0; x < 8; x++) q4[x] = qp[x];

    float4 acc[8];
#pragma unroll
    for (int x = 0; x < 8; x++) acc[x] = make_float4(0.f, 0.f, 0.f, 0.f);
    float m_i = -1e30f, l_i = 0.f;

    int nchunk = 2 * qt + 2;
    for (int kt = 0; kt < nchunk; kt++) {
        __syncthreads();
        for (int e = tid; e < 32 * HD / 4; e += 256) {
            size_t base = (size_t)(b * SEQ + kt * 32 + (e >> 5)) * KVD + kvh * HD + (e & 31) * 4;
            ((float4*)Ks)[e] = *(const float4*)(g_K + base);
            ((float4*)Vs)[e] = *(const float4*)(g_V + base);
        }
        __syncthreads();

        float p[32];
        float m_t = -1e30f;
#pragma unroll
        for (int j = 0; j < 32; j++) {
            const float4* kr = ((const float4*)Ks) + j * 32 + quad * 8;
            float s = 0.f;
#pragma unroll
            for (int x = 0; x < 8; x++) {
                float4 kv = kr[x];
                s += q4[x].x * kv.x + q4[x].y * kv.y + q4[x].z * kv.z + q4[x].w * kv.w;
            }
            s += __shfl_xor_sync(0xffffffffu, s, 1);
            s += __shfl_xor_sync(0xffffffffu, s, 2);
            s *= scale;
            if (kt * 32 + j > qglob) s = -1e30f;
            p[j] = s;
            m_t = fmaxf(m_t, s);
        }

        float m_new = fmaxf(m_i, m_t);
        float corr = expf(m_i - m_new);
        float lsum = 0.f;
#pragma unroll
        for (int j = 0; j < 32; j++) {
            p[j] = expf(p[j] - m_new);
            lsum += p[j];
        }
        l_i = l_i * corr + lsum;
        m_i = m_new;
#pragma unroll
        for (int x = 0; x < 8; x++) {
            acc[x].x *= corr; acc[x].y *= corr; acc[x].z *= corr; acc[x].w *= corr;
        }
#pragma unroll
        for (int j = 0; j < 32; j++) {
            float pj = p[j];
            const float4* vr = ((const float4*)Vs) + j * 32 + quad * 8;
#pragma unroll
            for (int x = 0; x < 8; x++) {
                float4 vv = vr[x];
                acc[x].x += pj * vv.x; acc[x].y += pj * vv.y;
                acc[x].z += pj * vv.z; acc[x].w += pj * vv.w;
            }
        }
    }
    float invl = 1.0f / l_i;
    float* op = g_A + (size_t)(b * SEQ + qglob) * HID + h * HD + quad * 32;
#pragma unroll
    for (int x = 0; x < 8; x++) {
        float4 vv = acc[x];
        vv.x *= invl; vv.y *= invl; vv.z *= invl; vv.w *= invl;
        *(float4*)(op + x * 4) = vv;
    }
}

extern "C" void kernel_launch(void* const* d_in, const int* in_sizes, int n_in,
                              void* d_out, int out_size) {
    const float* hidden = (const float*)d_in[0];
    const float* Wq = (const float*)d_in[1];
    const float* Wk = (const float*)d_in[2];
    const float* Wv = (const float*)d_in[3];
    const float* Wo = (const float*)d_in[4];
    float* out = (float*)d_out;

    long nH = (long)ROWS * HID;
    long nWq = (long)HID * HID;

    // splits for Q/O path only
    split_kernel<<<(unsigned)((nH + 255) / 256), 256>>>(hidden, -1, 0, 0, nH);
    split_kernel<<<(unsigned)((nWq + 255) / 256), 256>>>(Wq, -1, 1, 1, nWq);
    split_kernel<<<(unsigned)((nWq + 255) / 256), 256>>>(Wo, -1, 4, 1, nWq);

    // Q projection on tensor cores (smooth path, split-bf16 ok)
    bgemm_mma<<<dim3(HID / 128, ROWS / 128), 256>>>(0, 0, 0, nullptr, HID);

    // K/V projections in exact R5 fp32 (quant-sensitive path)
    sgemm_nt<<<dim3(KVD / 128, ROWS / 128), 256>>>(hidden, Wk, 1, ROWS, KVD, HID);
    sgemm_nt<<<dim3(KVD / 128, ROWS / 128), 256>>>(hidden, Wv, 2, ROWS, KVD, HID);

    // fake-quant (in place on g_K / g_V)
    quant_k_kernel<<<KVD, 512>>>();
    quant_v_kernel<<<ROWS, 256>>>();

    // RoPE on Q (32 heads) and quantized K (8 heads)
    int totQ = ROWS * NH * 64;
    int totK = ROWS * KVH * 64;
    rope_kernel<<<(totQ + 255) / 256, 256>>>(0, NH, totQ);
    rope_kernel<<<(totK + 255) / 256, 256>>>(1, KVH, totK);

    // attention: g_Q, g_K, g_V -> g_A
    attn_kernel<<<dim3(SEQ / 64, NH, BSZ), 256>>>();

    // output projection: split attn out (smooth), HMMA GEMM to external out
    split_kernel<<<(unsigned)((nH + 255) / 256), 256>>>(nullptr, 3, 5, 0, nH);
    bgemm_mma<<<dim3(HID / 128, ROWS / 128), 256>>>(1, 1, -1, out, HID);
}

// round 17
// speedup vs baseline: 2.4012x; 1.8997x over previous
#include <cuda_runtime.h>
#include <cuda_bf16.h>
#include <math.h>
#include <stdint.h>

#define BSZ 2
#define SEQ 1024
#define HID 4096
#define NH 32
#define KVH 8
#define HD 128
#define ROWS (BSZ*SEQ)      // 2048
#define KVD (KVH*HD)        // 1024
#define K3 (3*HID)          // 12288

// fp32 scratch
__device__ float g_Q[ROWS*HID];
__device__ float g_K[ROWS*KVD];
__device__ float g_V[ROWS*KVD];
__device__ float g_A[ROWS*HID];
// bf16 split buffers (Q/O projection path)
__device__ __nv_bfloat16 g_hs [ROWS*(size_t)K3];
__device__ __nv_bfloat16 g_as2[ROWS*(size_t)K3];
__device__ __nv_bfloat16 g_wq [HID*(size_t)K3];
__device__ __nv_bfloat16 g_wo [HID*(size_t)K3];
// bf16 split buffers for attention
__device__ __nv_bfloat16 g_Qhi[ROWS*(size_t)HID];
__device__ __nv_bfloat16 g_Qlo[ROWS*(size_t)HID];
__device__ __nv_bfloat16 g_Khi[ROWS*(size_t)KVD];
__device__ __nv_bfloat16 g_Klo[ROWS*(size_t)KVD];
__device__ __nv_bfloat16 g_VThi[ROWS*(size_t)KVD];  // [b][kvh][d][s]
__device__ __nv_bfloat16 g_VTlo[ROWS*(size_t)KVD];

__device__ __forceinline__ uint32_t s2u(const void* p) {
    uint32_t a;
    asm("{ .reg .u64 t; cvta.to.shared.u64 t, %1; cvt.u32.u64 %0, t; }" : "=r"(a) : "l"(p));
    return a;
}

__device__ __forceinline__ void cp16(uint32_t dst, const void* src) {
    asm volatile("cp.async.cg.shared.global [%0], [%1], 16;" :: "r"(dst), "l"(src));
}

__device__ __forceinline__ void mma16816(float* c, const uint32_t* a, const uint32_t* b) {
    asm volatile(
        "mma.sync.aligned.m16n8k16.row.col.f32.bf16.bf16.f32 "
        "{%0,%1,%2,%3}, {%4,%5,%6,%7}, {%8,%9}, {%0,%1,%2,%3};"
        : "+f"(c[0]), "+f"(c[1]), "+f"(c[2]), "+f"(c[3])
        : "r"(a[0]), "r"(a[1]), "r"(a[2]), "r"(a[3]), "r"(b[0]), "r"(b[1]));
}

__device__ __forceinline__ void ldmx4(uint32_t* r, uint32_t addr) {
    asm volatile("ldmatrix.sync.aligned.m8n8.x4.shared.b16 {%0,%1,%2,%3}, [%4];"
                 : "=r"(r[0]), "=r"(r[1]), "=r"(r[2]), "=r"(r[3]) : "r"(addr));
}
__device__ __forceinline__ void ldmx2(uint32_t* r, uint32_t addr) {
    asm volatile("ldmatrix.sync.aligned.m8n8.x2.shared.b16 {%0,%1}, [%2];"
                 : "=r"(r[0]), "=r"(r[1]) : "r"(addr));
}

__device__ __forceinline__ uint32_t packbf(float x, float y) {
    __nv_bfloat162 t;
    t.x = __float2bfloat16(x);
    t.y = __float2bfloat16(y);
    return *(uint32_t*)&t;
}

// ---------------- bf16 split for projection GEMMs ----------------
__global__ void split_kernel(const float* __restrict__ Xext, int in_id, int out_id,
                             int mode, long total) {
    long i = (long)blockIdx.x * blockDim.x + threadIdx.x;
    if (i >= total) return;
    const float* X = (in_id < 0) ? Xext : g_A;
    __nv_bfloat16* Y;
    switch (out_id) {
        case 0: Y = g_hs; break;
        case 1: Y = g_wq; break;
        case 4: Y = g_wo; break;
        default: Y = g_as2; break;
    }
    long r = i >> 12;
    long c = i & 4095;
    float x = X[i];
    __nv_bfloat16 hi = __float2bfloat16(x);
    __nv_bfloat16 lo = __float2bfloat16(x - __bfloat162float(hi));
    __nv_bfloat16* row = Y + r * (size_t)K3;
    if (mode == 0) {
        row[c] = hi; row[HID + c] = lo; row[2 * HID + c] = hi;
    } else {
        row[c] = hi; row[HID + c] = hi; row[2 * HID + c] = lo;
    }
}

// ---------------- hi/lo split (same layout): which 0 -> Q, 1 -> K ----------------
__global__ void hl_split(int which, long total) {
    long i = (long)blockIdx.x * blockDim.x + threadIdx.x;
    if (i >= total) return;
    const float* X = which ? g_K : g_Q;
    __nv_bfloat16* Hi = which ? g_Khi : g_Qhi;
    __nv_bfloat16* Lo = which ? g_Klo : g_Qlo;
    float x = X[i];
    __nv_bfloat16 hi = __float2bfloat16(x);
    __nv_bfloat16 lo = __float2bfloat16(x - __bfloat162float(hi));
    Hi[i] = hi; Lo[i] = lo;
}

// ---------------- V hi/lo split + transpose to [b][kvh][d][s] ----------------
__global__ void vt_split() {
    long i = (long)blockIdx.x * blockDim.x + threadIdx.x;
    if (i >= (long)ROWS * KVD) return;
    int s = (int)(i & (SEQ - 1));
    long t = i >> 10;
    int d = (int)(t & (HD - 1));
    int bk = (int)(t >> 7);
    int b = bk >> 3, kvh = bk & 7;
    float x = g_V[(size_t)(b * SEQ + s) * KVD + kvh * HD + d];
    __nv_bfloat16 hi = __float2bfloat16(x);
    __nv_bfloat16 lo = __float2bfloat16(x - __bfloat162float(hi));
    g_VThi[i] = hi; g_VTlo[i] = lo;
}

// ---------------- fp32 SGEMM (bit-identical to R5 path): C = A @ B^T ----------------
__global__ __launch_bounds__(256) void sgemm_nt(const float* __restrict__ A,
                                                const float* __restrict__ B,
                                                int c_id, int M, int N, int K) {
    float* C = (c_id == 1) ? g_K : g_V;
    const int BM = 128, BN = 128, BK = 8;
    __shared__ float As[BK][BM];
    __shared__ float Bs[BK][BN];
    int tid = threadIdx.x;
    int lr = tid >> 1;
    int lc = (tid & 1) * 4;
    int ty = tid >> 4;
    int tx = tid & 15;
    const float* Ab = A + (size_t)blockIdx.y * BM * K;
    const float* Bb = B + (size_t)blockIdx.x * BN * K;
    float acc[8][8];
#pragma unroll
    for (int i = 0; i < 8; i++)
#pragma unroll
        for (int j = 0; j < 8; j++) acc[i][j] = 0.f;

    for (int k0 = 0; k0 < K; k0 += BK) {
        float4 a4 = *(const float4*)(Ab + (size_t)lr * K + k0 + lc);
        float4 b4 = *(const float4*)(Bb + (size_t)lr * K + k0 + lc);
        As[lc + 0][lr] = a4.x; As[lc + 1][lr] = a4.y; As[lc + 2][lr] = a4.z; As[lc + 3][lr] = a4.w;
        Bs[lc + 0][lr] = b4.x; Bs[lc + 1][lr] = b4.y; Bs[lc + 2][lr] = b4.z; Bs[lc + 3][lr] = b4.w;
        __syncthreads();
#pragma unroll
        for (int k = 0; k < BK; k++) {
            float4 a0 = ((const float4*)As[k])[ty * 2];
            float4 a1 = ((const float4*)As[k])[ty * 2 + 1];
            float4 b0 = ((const float4*)Bs[k])[tx * 2];
            float4 b1 = ((const float4*)Bs[k])[tx * 2 + 1];
            float ar[8] = {a0.x, a0.y, a0.z, a0.w, a1.x, a1.y, a1.z, a1.w};
            float br[8] = {b0.x, b0.y, b0.z, b0.w, b1.x, b1.y, b1.z, b1.w};
#pragma unroll
            for (int i = 0; i < 8; i++)
#pragma unroll
                for (int j = 0; j < 8; j++) acc[i][j] += ar[i] * br[j];
        }
        __syncthreads();
    }
    float* Cb = C + (size_t)(blockIdx.y * BM + ty * 8) * N + blockIdx.x * BN + tx * 8;
#pragma unroll
    for (int i = 0; i < 8; i++) {
        float4 c0 = make_float4(acc[i][0], acc[i][1], acc[i][2], acc[i][3]);
        float4 c1 = make_float4(acc[i][4], acc[i][5], acc[i][6], acc[i][7]);
        *(float4*)(Cb + (size_t)i * N) = c0;
        *(float4*)(Cb + (size_t)i * N + 4) = c1;
    }
}

// ---------------- HMMA bf16 GEMM: C[M,N] = A[M,K3] @ B[N,K3]^T (Q and O) -------
#define SROWB 80
#define ABUF_B 10240
#define STAGE_B 20480

__global__ __launch_bounds__(256) void bgemm_mma(int a_id, int b_id, int c_id,
                                                 float* __restrict__ Cext, int N) {
    __shared__ __align__(16) unsigned char smbuf[2 * STAGE_B];
    const __nv_bfloat16* A = (a_id == 0) ? g_hs : g_as2;
    const __nv_bfloat16* B = (b_id == 0) ? g_wq : g_wo;
    float* C = (c_id < 0) ? Cext : g_Q;

    const int tid = threadIdx.x;
    const int lane = tid & 31;
    const int wid = tid >> 5;
    const int wm = (wid & 1) * 64;
    const int wn = (wid >> 1) * 32;
    const int m0g = blockIdx.y * 128;
    const int n0g = blockIdx.x * 128;
    const uint32_t smb = s2u(smbuf);

    const int lc = tid & 3;
    const int lr = tid >> 2;
    const __nv_bfloat16* aSrc0 = A + (size_t)(m0g + lr) * K3 + lc * 8;
    const __nv_bfloat16* aSrc1 = A + (size_t)(m0g + lr + 64) * K3 + lc * 8;
    const __nv_bfloat16* bSrc0 = B + (size_t)(n0g + lr) * K3 + lc * 8;
    const __nv_bfloat16* bSrc1 = B + (size_t)(n0g + lr + 64) * K3 + lc * 8;
    const uint32_t dA0 = (uint32_t)(lr * SROWB + lc * 16);
    const uint32_t dA1 = dA0 + 64 * SROWB;

    uint32_t aAddr[4], bAddr[4];
#pragma unroll
    for (int mt = 0; mt < 4; mt++)
        aAddr[mt] = smb + (uint32_t)((wm + mt * 16 + (lane & 15)) * SROWB + (lane >> 4) * 16);
#pragma unroll
    for (int nt = 0; nt < 4; nt++)
        bAddr[nt] = smb + ABUF_B +
                    (uint32_t)((wn + nt * 8 + (lane & 7)) * SROWB + ((lane >> 3) & 1) * 16);

    float acc[4][4][4];
#pragma unroll
    for (int mt = 0; mt < 4; mt++)
#pragma unroll
        for (int nt = 0; nt < 4; nt++)
#pragma unroll
            for (int x = 0; x < 4; x++) acc[mt][nt][x] = 0.f;

    const int NK = K3 / 32;

    {
        uint32_t sb = smb;
        cp16(sb + dA0, aSrc0);
        cp16(sb + dA1, aSrc1);
        cp16(sb + ABUF_B + dA0, bSrc0);
        cp16(sb + ABUF_B + dA1, bSrc1);
        asm volatile("cp.async.commit_group;");
    }

    for (int it = 0; it < NK; ++it) {
        const uint32_t boff = (uint32_t)(it & 1) * STAGE_B;
        if (it + 1 < NK) {
            const int k0 = (it + 1) * 32;
            const uint32_t sb = smb + (uint32_t)((it + 1) & 1) * STAGE_B;
            cp16(sb + dA0, aSrc0 + k0);
            cp16(sb + dA1, aSrc1 + k0);
            cp16(sb + ABUF_B + dA0, bSrc0 + k0);
            cp16(sb + ABUF_B + dA1, bSrc1 + k0);
            asm volatile("cp.async.commit_group;");
            asm volatile("cp.async.wait_group %0;" :: "n"(1));
        } else {
            asm volatile("cp.async.wait_group %0;" :: "n"(0));
        }
        __syncthreads();

#pragma unroll
        for (int kk = 0; kk < 2; kk++) {
            const uint32_t ko = boff + kk * 32;
            uint32_t a[4][4], b[4][2];
#pragma unroll
            for (int mt = 0; mt < 4; mt++) ldmx4(a[mt], aAddr[mt] + ko);
#pragma unroll
            for (int nt = 0; nt < 4; nt++) ldmx2(b[nt], bAddr[nt] + ko);
#pragma unroll
            for (int mt = 0; mt < 4; mt++)
#pragma unroll
                for (int nt = 0; nt < 4; nt++)
                    mma16816(acc[mt][nt], a[mt], b[nt]);
        }
        __syncthreads();
    }

#pragma unroll
    for (int mt = 0; mt < 4; mt++) {
        int r0 = m0g + wm + mt * 16 + (lane >> 2);
#pragma unroll
        for (int nt = 0; nt < 4; nt++) {
            int cc = n0g + wn + nt * 8 + (lane & 3) * 2;
            float2 v0 = make_float2(acc[mt][nt][0], acc[mt][nt][1]);
            float2 v1 = make_float2(acc[mt][nt][2], acc[mt][nt][3]);
            *(float2*)(C + (size_t)r0 * N + cc) = v0;
            *(float2*)(C + (size_t)(r0 + 8) * N + cc) = v1;
        }
    }
}

// ---------------- bitonic sort ----------------
__device__ __forceinline__ void bitonic_sort(float* s, int n) {
    for (int k = 2; k <= n; k <<= 1) {
        for (int j = k >> 1; j > 0; j >>= 1) {
            __syncthreads();
            for (int i = threadIdx.x; i < n; i += blockDim.x) {
                int ixj = i ^ j;
                if (ixj > i) {
                    float a = s[i], b = s[ixj];
                    bool up = ((i & k) == 0);
                    if ((a > b) == up) { s[i] = b; s[ixj] = a; }
                }
            }
        }
    }
    __syncthreads();
}

// ---------------- fake_quant_sparse on K ----------------
__global__ __launch_bounds__(512) void quant_k_kernel() {
    __shared__ float s[2048];
    __shared__ float red[64];
    __shared__ float stats[3];
    int col = blockIdx.x;
    int tid = threadIdx.x;
    float xv[4];
#pragma unroll
    for (int m = 0; m < 4; m++) {
        int i = tid + 512 * m;
        xv[m] = g_K[(size_t)i * KVD + col];
        s[i] = xv[m];
    }
    bitonic_sort(s, 2048);
    if (tid == 0) {
        float posU = 0.9995f * 2047.0f;
        int iU = (int)posU; float frU = posU - (float)iU;
        float posL = 0.0005f * 2047.0f;
        int iL = (int)posL; float frL = posL - (float)iL;
        stats[0] = s[iL] * (1.0f - frL) + s[iL + 1] * frL;
        stats[1] = s[iU] * (1.0f - frU) + s[iU + 1] * frU;
        stats[2] = s[1023];
    }
    __syncthreads();
    float lower = stats[0], upper = stats[1], med = stats[2];
    float mx = -1e30f, mn = 1e30f;
    bool msk[4];
#pragma unroll
    for (int m = 0; m < 4; m++) {
        msk[m] = (xv[m] <= lower) || (xv[m] >= upper);
        float tmp = msk[m] ? med : xv[m];
        mx = fmaxf(mx, tmp);
        mn = fminf(mn, tmp);
    }
#pragma unroll
    for (int o = 16; o > 0; o >>= 1) {
        mx = fmaxf(mx, __shfl_xor_sync(0xffffffffu, mx, o));
        mn = fminf(mn, __shfl_xor_sync(0xffffffffu, mn, o));
    }
    if ((tid & 31) == 0) { red[tid >> 5] = mx; red[32 + (tid >> 5)] = mn; }
    __syncthreads();
    if (tid == 0) {
        float M = -1e30f, Nn = 1e30f;
        for (int w = 0; w < 16; w++) { M = fmaxf(M, red[w]); Nn = fminf(Nn, red[32 + w]); }
        red[0] = M; red[32] = Nn;
    }
    __syncthreads();
    mx = red[0]; mn = red[32];
    float qx = 15.0f / (mx - mn);
    float offset = mn * qx;
#pragma unroll
    for (int m = 0; m < 4; m++) {
        if (!msk[m]) {
            float q = rintf(qx * xv[m] - offset);
            q = fminf(fmaxf(q, 0.0f), 15.0f);
            g_K[(size_t)(tid + 512 * m) * KVD + col] = (q + offset) / qx;
        }
    }
}

// ---------------- fake_quant_sparse on V ----------------
__global__ __launch_bounds__(256) void quant_v_kernel() {
    __shared__ float s[1024];
    __shared__ float red[64];
    __shared__ float stats[3];
    int r = blockIdx.x;
    int tid = threadIdx.x;
    float* row = g_V + (size_t)r * KVD;
    float xv[4];
#pragma unroll
    for (int m = 0; m < 4; m++) {
        int i = tid + 256 * m;
        xv[m] = row[i];
        s[i] = xv[m];
    }
    bitonic_sort(s, 1024);
    if (tid == 0) {
        float posU = 0.9995f * 1023.0f;
        int iU = (int)posU; float frU = posU - (float)iU;
        float posL = 0.0005f * 1023.0f;
        int iL = (int)posL; float frL = posL - (float)iL;
        stats[0] = s[iL] * (1.0f - frL) + s[iL + 1] * frL;
        stats[1] = s[iU] * (1.0f - frU) + s[iU + 1] * frU;
        stats[2] = s[511];
    }
    __syncthreads();
    float lower = stats[0], upper = stats[1], med = stats[2];
    float mx = -1e30f, mn = 1e30f;
    bool msk[4];
#pragma unroll
    for (int m = 0; m < 4; m++) {
        msk[m] = (xv[m] <= lower) || (xv[m] >= upper);
        float tmp = msk[m] ? med : xv[m];
        mx = fmaxf(mx, tmp);
        mn = fminf(mn, tmp);
    }
#pragma unroll
    for (int o = 16; o > 0; o >>= 1) {
        mx = fmaxf(mx, __shfl_xor_sync(0xffffffffu, mx, o));
        mn = fminf(mn, __shfl_xor_sync(0xffffffffu, mn, o));
    }
    if ((tid & 31) == 0) { red[tid >> 5] = mx; red[32 + (tid >> 5)] = mn; }
    __syncthreads();
    if (tid == 0) {
        float M = -1e30f, Nn = 1e30f;
        for (int w = 0; w < 8; w++) { M = fmaxf(M, red[w]); Nn = fminf(Nn, red[32 + w]); }
        red[0] = M; red[32] = Nn;
    }
    __syncthreads();
    mx = red[0]; mn = red[32];
    float qx = 15.0f / (mx - mn);
    float offset = mn * qx;
#pragma unroll
    for (int m = 0; m < 4; m++) {
        if (!msk[m]) {
            float q = rintf(qx * xv[m] - offset);
            q = fminf(fmaxf(q, 0.0f), 15.0f);
            row[tid + 256 * m] = (q + offset) / qx;
        }
    }
}

// ---------------- RoPE ----------------
__global__ void rope_kernel(int which, int nheads, int total) {
    int idx = blockIdx.x * blockDim.x + threadIdx.x;
    if (idx >= total) return;
    float* X = (which == 0) ? g_Q : g_K;
    int d = idx & 63;
    int t2 = idx >> 6;
    int h = t2 % nheads;
    int r = t2 / nheads;
    int pos = r & (SEQ - 1);
    double inv = exp(-((double)d / 64.0) * log(10000.0));
    double fr = (double)pos * inv;
    float c = (float)cos(fr);
    float sn = (float)sin(fr);
    float* p = X + (size_t)r * nheads * HD + h * HD + d;
    float x1 = p[0], x2 = p[64];
    p[0] = x1 * c - x2 * sn;
    p[64] = x2 * c + x1 * sn;
}

// ---------------- HMMA flash attention (split-bf16, fp32-accurate) ----------------
// grid (16, 32, 2), block 128 (4 warps; warp = 16 q-rows).
// smem: Q hi/lo swizzled 32KB (16KB per half) + 10KB K/V streaming buffer.
#define QHALF 16384

__global__ __launch_bounds__(128) void attn_mma() {
    __shared__ __align__(16) unsigned char Qsm[2 * QHALF];      // 32768
    __shared__ __align__(16) unsigned char KVsm[128 * 80];      // 10240
    const int qt = blockIdx.x, h = blockIdx.y, b = blockIdx.z;
    const int kvh = h >> 2;
    const int tid = threadIdx.x, lane = tid & 31, w = tid >> 5;
    const uint32_t qsb = s2u(Qsm), kvb = s2u(KVsm);
    const float scale = 0.08838834764831843f;

    // load Q tile hi/lo swizzled (16B chunk c of row r stored at c^(r&7))
#pragma unroll
    for (int half = 0; half < 2; half++) {
        const __nv_bfloat16* src = half ? g_Qlo : g_Qhi;
        for (int e = tid; e < 1024; e += 128) {
            int r = e >> 4, c = e & 15;
            uint4 v = *(const uint4*)(src + (size_t)(b * SEQ + qt * 64 + r) * HID + h * HD + c * 8);
            *(uint4*)(Qsm + half * QHALF + r * 256 + ((c ^ (r & 7)) * 16)) = v;
        }
    }

    const int g = lane >> 2, tig = lane & 3;
    const int row0 = qt * 64 + w * 16 + g;
    // ldmatrix A (Q) addressing
    const int a_r = w * 16 + ((lane >> 3) & 1) * 8 + (lane & 7);
    const int a_csel = lane >> 4;
    const int a_rx = a_r & 7;
    const uint32_t qrow_hi = qsb + a_r * 256;
    // ldmatrix B addressing pieces
    const int b_row = lane & 7;
    const int b_csel = (lane >> 3) & 1;

    float o[16][4];
#pragma unroll
    for (int nt = 0; nt < 16; nt++)
#pragma unroll
        for (int x = 0; x < 4; x++) o[nt][x] = 0.f;
    float m0 = -1e30f, m1 = -1e30f, l0 = 0.f, l1 = 0.f;

    const int nchunk = 2 * qt + 2;
    for (int kt = 0; kt < nchunk; kt++) {
        const int koff = kt * 32;
        float s[4][4];
#pragma unroll
        for (int nt = 0; nt < 4; nt++)
#pragma unroll
            for (int x = 0; x < 4; x++) s[nt][x] = 0.f;

        // ===== S pass 1: K-hi (Qhi+Qlo) =====
        __syncthreads();
        for (int e = tid; e < 512; e += 128) {
            int sr = e >> 4, c = e & 15;
            uint4 v = *(const uint4*)(g_Khi + (size_t)(b * SEQ + koff + sr) * KVD + kvh * HD + c * 8);
            *(uint4*)(KVsm + sr * 256 + ((c ^ (sr & 7)) * 16)) = v;
        }
        __syncthreads();
#pragma unroll
        for (int kst = 0; kst < 8; kst++) {
            uint32_t ksw = (uint32_t)(((kst * 2 + a_csel) ^ a_rx) * 16);
            uint32_t ah[4], al[4];
            ldmx4(ah, qrow_hi + ksw);
            ldmx4(al, qrow_hi + QHALF + ksw);
#pragma unroll
            for (int nt = 0; nt < 4; nt++) {
                int srow = nt * 8 + b_row;
                uint32_t bb[2];
                ldmx2(bb, kvb + srow * 256 + (((kst * 2 + b_csel) ^ (srow & 7)) * 16));
                mma16816(s[nt], ah, bb);
                mma16816(s[nt], al, bb);
            }
        }
        // ===== S pass 2: K-lo (Qhi only) =====
        __syncthreads();
        for (int e = tid; e < 512; e += 128) {
            int sr = e >> 4, c = e & 15;
            uint4 v = *(const uint4*)(g_Klo + (size_t)(b * SEQ + koff + sr) * KVD + kvh * HD + c * 8);
            *(uint4*)(KVsm + sr * 256 + ((c ^ (sr & 7)) * 16)) = v;
        }
        __syncthreads();
#pragma unroll
        for (int kst = 0; kst < 8; kst++) {
            uint32_t ksw = (uint32_t)(((kst * 2 + a_csel) ^ a_rx) * 16);
            uint32_t ah[4];
            ldmx4(ah, qrow_hi + ksw);
#pragma unroll
            for (int nt = 0; nt < 4; nt++) {
                int srow = nt * 8 + b_row;
                uint32_t bb[2];
                ldmx2(bb, kvb + srow * 256 + (((kst * 2 + b_csel) ^ (srow & 7)) * 16));
                mma16816(s[nt], ah, bb);
            }
        }

        // ===== scale + causal mask + online softmax =====
        float mt0 = -1e30f, mt1 = -1e30f;
#pragma unroll
        for (int nt = 0; nt < 4; nt++) {
#pragma unroll
            for (int cc = 0; cc < 2; cc++) {
                int j = koff + nt * 8 + tig * 2 + cc;
                float v0 = s[nt][cc] * scale;
                float v1 = s[nt][2 + cc] * scale;
                if (j > row0) v0 = -1e30f;
                if (j > row0 + 8) v1 = -1e30f;
                s[nt][cc] = v0; s[nt][2 + cc] = v1;
                mt0 = fmaxf(mt0, v0); mt1 = fmaxf(mt1, v1);
            }
        }
        mt0 = fmaxf(mt0, __shfl_xor_sync(0xffffffffu, mt0, 1));
        mt0 = fmaxf(mt0, __shfl_xor_sync(0xffffffffu, mt0, 2));
        mt1 = fmaxf(mt1, __shfl_xor_sync(0xffffffffu, mt1, 1));
        mt1 = fmaxf(mt1, __shfl_xor_sync(0xffffffffu, mt1, 2));
        float mn0 = fmaxf(m0, mt0), mn1 = fmaxf(m1, mt1);
        float c0 = expf(m0 - mn0), c1 = expf(m1 - mn1);
        float sum0 = 0.f, sum1 = 0.f;
#pragma unroll
        for (int nt = 0; nt < 4; nt++) {
#pragma unroll
            for (int cc = 0; cc < 2; cc++) {
                float p0 = expf(s[nt][cc] - mn0);
                float p1 = expf(s[nt][2 + cc] - mn1);
                s[nt][cc] = p0; s[nt][2 + cc] = p1;
                sum0 += p0; sum1 += p1;
            }
        }
        sum0 += __shfl_xor_sync(0xffffffffu, sum0, 1);
        sum0 += __shfl_xor_sync(0xffffffffu, sum0, 2);
        sum1 += __shfl_xor_sync(0xffffffffu, sum1, 1);
        sum1 += __shfl_xor_sync(0xffffffffu, sum1, 2);
        l0 = l0 * c0 + sum0; l1 = l1 * c1 + sum1;
        m0 = mn0; m1 = mn1;
#pragma unroll
        for (int nt = 0; nt < 16; nt++) {
            o[nt][0] *= c0; o[nt][1] *= c0;
            o[nt][2] *= c1; o[nt][3] *= c1;
        }

        // ===== P repack to A-frags (hi + lo) =====
        uint32_t aPhi[2][4], aPlo[2][4];
#pragma unroll
        for (int ks = 0; ks < 2; ks++) {
            int n0 = ks * 2, n1 = ks * 2 + 1;
            float p00 = s[n0][0], p01 = s[n0][1], p02 = s[n0][2], p03 = s[n0][3];
            float p10 = s[n1][0], p11 = s[n1][1], p12 = s[n1][2], p13 = s[n1][3];
            uint32_t h0 = packbf(p00, p01), h1 = packbf(p02, p03);
            uint32_t h2 = packbf(p10, p11), h3 = packbf(p12, p13);
            aPhi[ks][0] = h0; aPhi[ks][1] = h1; aPhi[ks][2] = h2; aPhi[ks][3] = h3;
            __nv_bfloat162* hv;
            hv = (__nv_bfloat162*)&h0;
            aPlo[ks][0] = packbf(p00 - __bfloat162float(hv->x), p01 - __bfloat162float(hv->y));
            hv = (__nv_bfloat162*)&h1;
            aPlo[ks][1] = packbf(p02 - __bfloat162float(hv->x), p03 - __bfloat162float(hv->y));
            hv = (__nv_bfloat162*)&h2;
            aPlo[ks][2] = packbf(p10 - __bfloat162float(hv->x), p11 - __bfloat162float(hv->y));
            hv = (__nv_bfloat162*)&h3;
            aPlo[ks][3] = packbf(p12 - __bfloat162float(hv->x), p13 - __bfloat162float(hv->y));
        }

        // ===== PV pass 1: V-hi (Phi + Plo) =====
        __syncthreads();
        for (int e = tid; e < 512; e += 128) {
            int d = e >> 2, c = e & 3;
            uint4 v = *(const uint4*)(g_VThi + ((size_t)((b * KVH + kvh) * HD + d)) * SEQ + koff + c * 8);
            *(uint4*)(KVsm + d * 80 + c * 16) = v;
        }
        __syncthreads();
#pragma unroll
        for (int ks = 0; ks < 2; ks++) {
#pragma unroll
            for (int nt = 0; nt < 16; nt++) {
                uint32_t bb[2];
                ldmx2(bb, kvb + (nt * 8 + b_row) * 80 + ((ks * 2 + b_csel) * 16));
                mma16816(o[nt], aPhi[ks], bb);
                mma16816(o[nt], aPlo[ks], bb);
            }
        }
        // ===== PV pass 2: V-lo (Phi only) =====
        __syncthreads();
        for (int e = tid; e < 512; e += 128) {
            int d = e >> 2, c = e & 3;
            uint4 v = *(const uint4*)(g_VTlo + ((size_t)((b * KVH + kvh) * HD + d)) * SEQ + koff + c * 8);
            *(uint4*)(KVsm + d * 80 + c * 16) = v;
        }
        __syncthreads();
#pragma unroll
        for (int ks = 0; ks < 2; ks++) {
#pragma unroll
            for (int nt = 0; nt < 16; nt++) {
                uint32_t bb[2];
                ldmx2(bb, kvb + (nt * 8 + b_row) * 80 + ((ks * 2 + b_csel) * 16));
                mma16816(o[nt], aPhi[ks], bb);
            }
        }
    }

    // epilogue
    float inv0 = 1.0f / l0, inv1 = 1.0f / l1;
    float* base0 = g_A + (size_t)(b * SEQ + row0) * HID + h * HD + tig * 2;
    float* base1 = g_A + (size_t)(b * SEQ + row0 + 8) * HID + h * HD + tig * 2;
#pragma unroll
    for (int nt = 0; nt < 16; nt++) {
        *(float2*)(base0 + nt * 8) = make_float2(o[nt][0] * inv0, o[nt][1] * inv0);
        *(float2*)(base1 + nt * 8) = make_float2(o[nt][2] * inv1, o[nt][3] * inv1);
    }
}

extern "C" void kernel_launch(void* const* d_in, const int* in_sizes, int n_in,
                              void* d_out, int out_size) {
    const float* hidden = (const float*)d_in[0];
    const float* Wq = (const float*)d_in[1];
    const float* Wk = (const float*)d_in[2];
    const float* Wv = (const float*)d_in[3];
    const float* Wo = (const float*)d_in[4];
    float* out = (float*)d_out;

    long nH = (long)ROWS * HID;
    long nWq = (long)HID * HID;
    long nKV = (long)ROWS * KVD;

    // splits for Q/O projection path
    split_kernel<<<(unsigned)((nH + 255) / 256), 256>>>(hidden, -1, 0, 0, nH);
    split_kernel<<<(unsigned)((nWq + 255) / 256), 256>>>(Wq, -1, 1, 1, nWq);
    split_kernel<<<(unsigned)((nWq + 255) / 256), 256>>>(Wo, -1, 4, 1, nWq);

    // Q projection on tensor cores
    bgemm_mma<<<dim3(HID / 128, ROWS / 128), 256>>>(0, 0, 0, nullptr, HID);

    // K/V projections exact fp32 (quant-sensitive)
    sgemm_nt<<<dim3(KVD / 128, ROWS / 128), 256>>>(hidden, Wk, 1, ROWS, KVD, HID);
    sgemm_nt<<<dim3(KVD / 128, ROWS / 128), 256>>>(hidden, Wv, 2, ROWS, KVD, HID);

    // fake-quant
    quant_k_kernel<<<KVD, 512>>>();
    quant_v_kernel<<<ROWS, 256>>>();

    // RoPE
    int totQ = ROWS * NH * 64;
    int totK = ROWS * KVH * 64;
    rope_kernel<<<(totQ + 255) / 256, 256>>>(0, NH, totQ);
    rope_kernel<<<(totK + 255) / 256, 256>>>(1, KVH, totK);

    // hi/lo splits for attention operands
    hl_split<<<(unsigned)((nH + 255) / 256), 256>>>(0, nH);
    hl_split<<<(unsigned)((nKV + 255) / 256), 256>>>(1, nKV);
    vt_split<<<(unsigned)((nKV + 255) / 256), 256>>>();

    // HMMA flash attention -> g_A
    attn_mma<<<dim3(SEQ / 64, NH, BSZ), 128>>>();

    // output projection
    split_kernel<<<(unsigned)((nH + 255) / 256), 256>>>(nullptr, 3, 5, 0, nH);
    bgemm_mma<<<dim3(HID / 128, ROWS / 128), 256>>>(1, 1, -1, out, HID);
}